// round 11
// baseline (speedup 1.0000x reference)
#include <cuda_runtime.h>
#include <cstdint>
#include <cstddef>

// Problem constants
static const int B  = 512;
static const int S  = 100;
static const int H  = 256;

#define TINYF 1.17549435e-38f

// ---------------- scratch (device globals; no allocations allowed) ----------------
__device__ float d_enc [512 * 100 * 256];              // [b][s][h]
__device__ float d_refg[512 * 100 * 256];              // [b][s][h]
__device__ float d_refp[512 * 100 * 256];              // [b][s][h]
__device__ float d_h[512 * 256];                       // encoder final h
__device__ float d_c[512 * 256];                       // encoder final c
__device__ float d_gum[100 * 512 * 100];               // gumbel noise per (t,b,s)
__device__ float d_Menc[2 * 1024];                     // emb @ enc_Wih^T   (rank-2 factor)
__device__ float d_Mdec[2 * 1024];                     // emb @ dec_Wih^T
__device__ float d_xstart[1024];                       // start @ dec_Wih^T

// ---------------- helpers ----------------
__device__ __forceinline__ float sigf(float x) { return 1.0f / (1.0f + expf(-x)); }
__device__ __forceinline__ float neg_inf() { return __int_as_float((int)0xff800000); }

// Threefry-2x32, 20 rounds (matches JAX threefry2x32_p)
__device__ __forceinline__ void threefry2x32(uint32_t k0, uint32_t k1,
                                             uint32_t x0, uint32_t x1,
                                             uint32_t* o0, uint32_t* o1)
{
    uint32_t ks2 = k0 ^ k1 ^ 0x1BD11BDAu;
#define TFR(r) { x0 += x1; x1 = (x1 << (r)) | (x1 >> (32 - (r))); x1 ^= x0; }
    x0 += k0;  x1 += k1;
    TFR(13) TFR(15) TFR(26) TFR(6)
    x0 += k1;  x1 += ks2 + 1u;
    TFR(17) TFR(29) TFR(16) TFR(24)
    x0 += ks2; x1 += k0 + 2u;
    TFR(13) TFR(15) TFR(26) TFR(6)
    x0 += k0;  x1 += k1 + 3u;
    TFR(17) TFR(29) TFR(16) TFR(24)
    x0 += k1;  x1 += ks2 + 4u;
    TFR(13) TFR(15) TFR(26) TFR(6)
    x0 += ks2; x1 += k0 + 5u;
#undef TFR
    *o0 = x0; *o1 = x1;
}

// ---------------- gumbel noise ----------------
__global__ void gumbelk()
{
    int i = blockIdx.x * blockDim.x + threadIdx.x;
    if (i >= S * B * S) return;
    int step   = i / (B * S);
    uint32_t n = (uint32_t)(i - step * (B * S));
    uint32_t k0, k1;
    threefry2x32(0u, 1u, 0u, (uint32_t)step, &k0, &k1);
    uint32_t a, bb;
    threefry2x32(k0, k1, 0u, n, &a, &bb);
    uint32_t bits = a ^ bb;
    float f = __uint_as_float((bits >> 9) | 0x3f800000u) - 1.0f;
    float u = fmaxf(TINYF, f + TINYF);
    d_gum[i] = -logf(-logf(u));
}

// ---------------- tiny precompute: rank-2 factors + start projection ----------------
__global__ void precompk(const float* __restrict__ emb,
                         const float* __restrict__ enc_Wih,
                         const float* __restrict__ dec_Wih,
                         const float* __restrict__ start)
{
    int j = blockIdx.x * blockDim.x + threadIdx.x;
    if (j >= 1024) return;
    float m0 = 0.f, m1 = 0.f, n0 = 0.f, n1 = 0.f, xs = 0.f;
    for (int e = 0; e < 256; e++) {
        float we = enc_Wih[(size_t)j * 256 + e];
        float wd = dec_Wih[(size_t)j * 256 + e];
        m0 = fmaf(emb[e],       we, m0);
        m1 = fmaf(emb[256 + e], we, m1);
        n0 = fmaf(emb[e],       wd, n0);
        n1 = fmaf(emb[256 + e], wd, n1);
        xs = fmaf(start[e],     wd, xs);
    }
    d_Menc[j] = m0; d_Menc[1024 + j] = m1;
    d_Mdec[j] = n0; d_Mdec[1024 + j] = n1;
    d_xstart[j] = xs;
}

// ================= persistent encoder + fused ref projections =====================
// 128 blocks x 1024 threads, 4 batch rows/block.
// Gates phase: thread owns gate column tid (full K, no reduction).
// Cell + ref phases: thread owns (row r4 = tid>>8, unit hh = tid&255).
__global__ void __launch_bounds__(1024)
encoderk(const float* __restrict__ inputs,
         const float* __restrict__ Whh,
         const float* __restrict__ bih, const float* __restrict__ bhh,
         const float* __restrict__ gWr, const float* __restrict__ gbr,
         const float* __restrict__ pWr, const float* __restrict__ pbr)
{
    const int tid = threadIdx.x;
    const int r4  = tid >> 8;
    const int hh  = tid & 255;
    const int b0  = blockIdx.x * 4;

    __shared__ __align__(16) float hs[4][256];
    __shared__ __align__(16) float gbuf[4][1024];

    float creg = 0.0f;                                  // c state of (r4, hh)
    const float me0 = d_Menc[tid], me1 = d_Menc[1024 + tid];
    const float bi1 = bih[tid],    bi2 = bhh[tid];
    const float gbr_t = gbr[hh];
    const float pbr_t = pbr[hh];

    ((float*)hs)[tid] = 0.0f;
    __syncthreads();

    for (int s = 0; s < S; s++) {
        // ---- gates: column tid, rows 0..3, full K=256 ----
        float a0c = 0.f, a1c = 0.f, a2c = 0.f, a3c = 0.f;
        const float* wrow = Whh + (size_t)tid * 256;
#pragma unroll 2
        for (int kg = 0; kg < 64; kg++) {
            int k = kg * 4;
            float4 w  = *(const float4*)(wrow + k);
            float4 x0 = *(const float4*)&hs[0][k];
            float4 x1 = *(const float4*)&hs[1][k];
            float4 x2 = *(const float4*)&hs[2][k];
            float4 x3 = *(const float4*)&hs[3][k];
            a0c = fmaf(w.x, x0.x, a0c); a0c = fmaf(w.y, x0.y, a0c);
            a0c = fmaf(w.z, x0.z, a0c); a0c = fmaf(w.w, x0.w, a0c);
            a1c = fmaf(w.x, x1.x, a1c); a1c = fmaf(w.y, x1.y, a1c);
            a1c = fmaf(w.z, x1.z, a1c); a1c = fmaf(w.w, x1.w, a1c);
            a2c = fmaf(w.x, x2.x, a2c); a2c = fmaf(w.y, x2.y, a2c);
            a2c = fmaf(w.z, x2.z, a2c); a2c = fmaf(w.w, x2.w, a2c);
            a3c = fmaf(w.x, x3.x, a3c); a3c = fmaf(w.y, x3.y, a3c);
            a3c = fmaf(w.z, x3.z, a3c); a3c = fmaf(w.w, x3.w, a3c);
        }
        float accv[4] = {a0c, a1c, a2c, a3c};
#pragma unroll
        for (int r = 0; r < 4; r++) {
            int b = b0 + r;
            float i0 = inputs[((size_t)b * 2 + 0) * S + s];
            float i1 = inputs[((size_t)b * 2 + 1) * S + s];
            float xv = fmaf(i1, me1, i0 * me0);
            gbuf[r][tid] = accv[r] + ((xv + bi1) + bi2);   // R10 encoder epilogue order
        }
        __syncthreads();

        // ---- cell: (r4, hh) ----
        {
            float ig = sigf(gbuf[r4][hh]);
            float fg = sigf(gbuf[r4][256 + hh]);
            float gg = tanhf(gbuf[r4][512 + hh]);
            float og = sigf(gbuf[r4][768 + hh]);
            float c  = fg * creg + ig * gg;
            creg = c;
            float h = og * tanhf(c);
            hs[r4][hh] = h;
            d_enc[((size_t)(b0 + r4) * S + s) * H + hh] = h;
        }
        __syncthreads();

        // ---- fused ref projections of h_s: (r4, hh), full K, no reduction ----
        {
            float rg = 0.f, rp = 0.f;
            const float* wg = gWr + (size_t)hh * 256;
            const float* wp = pWr + (size_t)hh * 256;
#pragma unroll 2
            for (int kg = 0; kg < 64; kg++) {
                int k = kg * 4;
                float4 hv = *(const float4*)&hs[r4][k];
                float4 ag = *(const float4*)(wg + k);
                float4 ap = *(const float4*)(wp + k);
                rg = fmaf(ag.x, hv.x, rg); rg = fmaf(ag.y, hv.y, rg);
                rg = fmaf(ag.z, hv.z, rg); rg = fmaf(ag.w, hv.w, rg);
                rp = fmaf(ap.x, hv.x, rp); rp = fmaf(ap.y, hv.y, rp);
                rp = fmaf(ap.z, hv.z, rp); rp = fmaf(ap.w, hv.w, rp);
            }
            size_t o = ((size_t)(b0 + r4) * S + s) * H + hh;
            d_refg[o] = rg + gbr_t;
            d_refp[o] = rp + pbr_t;
        }
        // no sync needed here: next gates phase only READS hs; the next hs write
        // (cell of s+1) is behind the sync after gates(s+1).
    }
    d_h[(size_t)(b0 + r4) * H + hh] = hs[r4][hh];
    d_c[(size_t)(b0 + r4) * H + hh] = creg;
}

// ================= persistent decoder: 4 rows/block, 1024 threads =================
__global__ void __launch_bounds__(1024)
decoderk(const float* __restrict__ inputs,
         const float* __restrict__ Whh,
         const float* __restrict__ bih, const float* __restrict__ bhh,
         const float* __restrict__ gWq, const float* __restrict__ gbq,
         const float* __restrict__ gV,
         const float* __restrict__ pWq, const float* __restrict__ pbq,
         const float* __restrict__ pV,
         float* __restrict__ out_probs, float* __restrict__ out_idx)
{
    const int tid  = threadIdx.x;
    const int lane = tid & 31;
    const int w    = tid >> 5;            // 0..31
    const int r4   = tid >> 8;            // 0..3  (row owner for combine/cell)
    const int hh   = tid & 255;
    const int qid  = tid >> 8;            // quarter for K/S splits (alias of r4)
    const int b0   = blockIdx.x * 4;

    __shared__ __align__(16) float hs [4][256];
    __shared__ __align__(16) float qs [4][256];     // qq, then readout q
    __shared__ __align__(16) float qps[4][256];
    __shared__ __align__(16) float gbuf[4][1024];   // gates / reduction scratch
    __shared__ float lgm[4][100];
    __shared__ float pr [4][100];
    __shared__ float sa0[4], sa1[4];
    __shared__ unsigned char msk[4][104];

    float creg;                                      // c state of (r4, hh)

    // hoisted constants
    const float md0 = d_Mdec[tid], md1 = d_Mdec[1024 + tid];
    const float bi1 = bih[tid],    bi2 = bhh[tid];
    const float xst = d_xstart[tid];
    const float gbq_t = gbq[hh];
    const float pbq_t = pbq[hh];

    hs[r4][hh] = d_h[(size_t)(b0 + r4) * H + hh];
    creg       = d_c[(size_t)(b0 + r4) * H + hh];
    for (int i = tid; i < 4 * 100; i += 1024) msk[i / 100][i % 100] = 0;
    __syncthreads();

    for (int t = 0; t < S; t++) {
        // ======== LSTM gates: column tid, rows 0..3, full K=256 ========
        {
            float a0c = 0.f, a1c = 0.f, a2c = 0.f, a3c = 0.f;
            const float* wrow = Whh + (size_t)tid * 256;
#pragma unroll 2
            for (int kg = 0; kg < 64; kg++) {
                int k = kg * 4;
                float4 wv = *(const float4*)(wrow + k);
                float4 x0 = *(const float4*)&hs[0][k];
                float4 x1 = *(const float4*)&hs[1][k];
                float4 x2 = *(const float4*)&hs[2][k];
                float4 x3 = *(const float4*)&hs[3][k];
                a0c = fmaf(wv.x, x0.x, a0c); a0c = fmaf(wv.y, x0.y, a0c);
                a0c = fmaf(wv.z, x0.z, a0c); a0c = fmaf(wv.w, x0.w, a0c);
                a1c = fmaf(wv.x, x1.x, a1c); a1c = fmaf(wv.y, x1.y, a1c);
                a1c = fmaf(wv.z, x1.z, a1c); a1c = fmaf(wv.w, x1.w, a1c);
                a2c = fmaf(wv.x, x2.x, a2c); a2c = fmaf(wv.y, x2.y, a2c);
                a2c = fmaf(wv.z, x2.z, a2c); a2c = fmaf(wv.w, x2.w, a2c);
                a3c = fmaf(wv.x, x3.x, a3c); a3c = fmaf(wv.y, x3.y, a3c);
                a3c = fmaf(wv.z, x3.z, a3c); a3c = fmaf(wv.w, x3.w, a3c);
            }
            float accv[4] = {a0c, a1c, a2c, a3c};
#pragma unroll
            for (int r = 0; r < 4; r++) {
                float xv = (t == 0) ? xst : fmaf(sa1[r], md1, sa0[r] * md0);
                gbuf[r][tid] = ((accv[r] + xv) + bi1) + bi2;   // R10 decoder order
            }
        }
        __syncthreads();

        // ======== LSTM cell: (r4, hh) ========
        {
            float ig = sigf(gbuf[r4][hh]);
            float fg = sigf(gbuf[r4][256 + hh]);
            float gg = tanhf(gbuf[r4][512 + hh]);
            float og = sigf(gbuf[r4][768 + hh]);
            float c  = fg * creg + ig * gg;
            creg = c;
            hs[r4][hh] = og * tanhf(c);
        }
        __syncthreads();

        // ======== qq partials: quarter qid, K in [qid*64, qid*64+64) ========
        {
            float a[4] = {0.f, 0.f, 0.f, 0.f};
            const float* wrow = gWq + (size_t)hh * 256 + qid * 64;
#pragma unroll 2
            for (int kg = 0; kg < 16; kg++) {
                int k = kg * 4;
                float4 wv = *(const float4*)(wrow + k);
#pragma unroll
                for (int r = 0; r < 4; r++) {
                    float4 hv = *(const float4*)&hs[r][qid * 64 + k];
                    a[r] = fmaf(wv.x, hv.x, a[r]); a[r] = fmaf(wv.y, hv.y, a[r]);
                    a[r] = fmaf(wv.z, hv.z, a[r]); a[r] = fmaf(wv.w, hv.w, a[r]);
                }
            }
#pragma unroll
            for (int r = 0; r < 4; r++) gbuf[qid][r * 256 + hh] = a[r];
        }
        __syncthreads();
        // combine: (r4, hh)
        qs[r4][hh] = ((gbuf[0][r4 * 256 + hh] + gbuf[1][r4 * 256 + hh]) +
                      (gbuf[2][r4 * 256 + hh] + gbuf[3][r4 * 256 + hh])) + gbq_t;
        __syncthreads();

        // ======== glimpse logits: 32 warps, r = w>>3, 13 s-positions each ========
        {
            int r  = w >> 3;
            int s0 = (w & 7) * 13;
            float qv[8];
#pragma unroll
            for (int k = 0; k < 8; k++) qv[k] = qs[r][k * 32 + lane];
            for (int si = 0; si < 13; si++) {
                int s = s0 + si;
                if (s >= 100) break;
                const float* rp = &d_refg[(((size_t)(b0 + r)) * S + s) * H];
                float sum = 0.0f;
#pragma unroll
                for (int k = 0; k < 8; k++)
                    sum = fmaf(__ldg(&gV[k * 32 + lane]),
                               tanhf(qv[k] + __ldg(&rp[k * 32 + lane])), sum);
#pragma unroll
                for (int o = 16; o > 0; o >>= 1) sum += __shfl_xor_sync(0xffffffffu, sum, o);
                if (lane == 0) lgm[r][s] = msk[r][s] ? neg_inf() : sum;
            }
        }
        __syncthreads();

        // ======== glimpse softmax -> pr (bit-identical to R10) ========
        if (w < 4) {
            int r = w;
            float v[4];
#pragma unroll
            for (int j = 0; j < 4; j++) {
                int s = lane + 32 * j;
                v[j] = (s < 100) ? lgm[r][s] : neg_inf();
            }
            float m = fmaxf(fmaxf(v[0], v[1]), fmaxf(v[2], v[3]));
#pragma unroll
            for (int o = 16; o > 0; o >>= 1) m = fmaxf(m, __shfl_xor_sync(0xffffffffu, m, o));
            float e[4];
#pragma unroll
            for (int j = 0; j < 4; j++) {
                int s = lane + 32 * j;
                e[j] = (s < 100) ? expf(v[j] - m) : 0.0f;
            }
            float sum = (e[0] + e[2]) + (e[1] + e[3]);
#pragma unroll
            for (int o = 16; o > 0; o >>= 1) sum += __shfl_xor_sync(0xffffffffu, sum, o);
#pragma unroll
            for (int j = 0; j < 4; j++) {
                int s = lane + 32 * j;
                if (s < 100) pr[r][s] = e[j] / sum;
            }
        }
        __syncthreads();

        // ======== readout partials: quarter qid, s in [qid*25, qid*25+25) ========
        {
            float a[4] = {0.f, 0.f, 0.f, 0.f};
            int sBase = qid * 25;
            for (int si = 0; si < 25; si++) {
                int s = sBase + si;
#pragma unroll
                for (int r = 0; r < 4; r++)
                    a[r] = fmaf(pr[r][s],
                                __ldg(&d_enc[(((size_t)(b0 + r)) * S + s) * H + hh]),
                                a[r]);
            }
#pragma unroll
            for (int r = 0; r < 4; r++) gbuf[qid][r * 256 + hh] = a[r];
        }
        __syncthreads();
        qs[r4][hh] = (gbuf[0][r4 * 256 + hh] + gbuf[1][r4 * 256 + hh]) +
                     (gbuf[2][r4 * 256 + hh] + gbuf[3][r4 * 256 + hh]);
        __syncthreads();

        // ======== qp partials: quarter qid over K ========
        {
            float a[4] = {0.f, 0.f, 0.f, 0.f};
            const float* wrow = pWq + (size_t)hh * 256 + qid * 64;
#pragma unroll 2
            for (int kg = 0; kg < 16; kg++) {
                int k = kg * 4;
                float4 wv = *(const float4*)(wrow + k);
#pragma unroll
                for (int r = 0; r < 4; r++) {
                    float4 hv = *(const float4*)&qs[r][qid * 64 + k];
                    a[r] = fmaf(wv.x, hv.x, a[r]); a[r] = fmaf(wv.y, hv.y, a[r]);
                    a[r] = fmaf(wv.z, hv.z, a[r]); a[r] = fmaf(wv.w, hv.w, a[r]);
                }
            }
#pragma unroll
            for (int r = 0; r < 4; r++) gbuf[qid][r * 256 + hh] = a[r];
        }
        __syncthreads();
        qps[r4][hh] = ((gbuf[0][r4 * 256 + hh] + gbuf[1][r4 * 256 + hh]) +
                       (gbuf[2][r4 * 256 + hh] + gbuf[3][r4 * 256 + hh])) + pbq_t;
        __syncthreads();

        // ======== pointer logits ========
        {
            int r  = w >> 3;
            int s0 = (w & 7) * 13;
            float qv[8];
#pragma unroll
            for (int k = 0; k < 8; k++) qv[k] = qps[r][k * 32 + lane];
            for (int si = 0; si < 13; si++) {
                int s = s0 + si;
                if (s >= 100) break;
                const float* rp = &d_refp[(((size_t)(b0 + r)) * S + s) * H];
                float sum = 0.0f;
#pragma unroll
                for (int k = 0; k < 8; k++)
                    sum = fmaf(__ldg(&pV[k * 32 + lane]),
                               tanhf(qv[k] + __ldg(&rp[k * 32 + lane])), sum);
#pragma unroll
                for (int o = 16; o > 0; o >>= 1) sum += __shfl_xor_sync(0xffffffffu, sum, o);
                if (lane == 0) lgm[r][s] = msk[r][s] ? neg_inf() : (10.0f * tanhf(sum));
            }
        }
        __syncthreads();

        // ======== sample (bit-identical to R10) ========
        if (w < 4) {
            int r = w;
            int b = b0 + r;
            float v[4];
#pragma unroll
            for (int j = 0; j < 4; j++) {
                int s = lane + 32 * j;
                v[j] = (s < 100) ? lgm[r][s] : neg_inf();
            }
            float bv = neg_inf(); int bi = 0;
#pragma unroll
            for (int j = 0; j < 4; j++) {
                int s = lane + 32 * j;
                if (s < 100) {
                    float y = v[j] + d_gum[((size_t)t * B + b) * S + s];
                    if (y > bv) { bv = y; bi = s; }
                }
            }
#pragma unroll
            for (int o = 16; o > 0; o >>= 1) {
                float vo = __shfl_xor_sync(0xffffffffu, bv, o);
                int   io = __shfl_xor_sync(0xffffffffu, bi, o);
                if (vo > bv || (vo == bv && io < bi)) { bv = vo; bi = io; }
            }
            float m = fmaxf(fmaxf(v[0], v[1]), fmaxf(v[2], v[3]));
#pragma unroll
            for (int o = 16; o > 0; o >>= 1) m = fmaxf(m, __shfl_xor_sync(0xffffffffu, m, o));
            float e[4];
#pragma unroll
            for (int j = 0; j < 4; j++) {
                int s = lane + 32 * j;
                e[j] = (s < 100) ? expf(v[j] - m) : 0.0f;
            }
            float sum = (e[0] + e[2]) + (e[1] + e[3]);
#pragma unroll
            for (int o = 16; o > 0; o >>= 1) sum += __shfl_xor_sync(0xffffffffu, sum, o);
#pragma unroll
            for (int j = 0; j < 4; j++) {
                int s = lane + 32 * j;
                if (s < 100) out_probs[((size_t)t * B + b) * S + s] = e[j] / sum;
            }
            if (lane == 0) {
                msk[r][bi] = 1;
                out_idx[(size_t)t * B + b] = (float)bi;
                sa0[r] = inputs[((size_t)b * 2 + 0) * S + bi];
                sa1[r] = inputs[((size_t)b * 2 + 1) * S + bi];
            }
        }
        __syncthreads();
    }
}

// ---------------- host ----------------
extern "C" void kernel_launch(void* const* d_in, const int* in_sizes, int n_in,
                              void* d_out, int out_size)
{
    (void)in_sizes; (void)n_in; (void)out_size;
    const float* inputs  = (const float*)d_in[0];
    const float* emb     = (const float*)d_in[1];
    const float* enc_Wih = (const float*)d_in[2];
    const float* enc_Whh = (const float*)d_in[3];
    const float* enc_bih = (const float*)d_in[4];
    const float* enc_bhh = (const float*)d_in[5];
    const float* dec_Wih = (const float*)d_in[6];
    const float* dec_Whh = (const float*)d_in[7];
    const float* dec_bih = (const float*)d_in[8];
    const float* dec_bhh = (const float*)d_in[9];
    const float* g_Wq    = (const float*)d_in[10];
    const float* g_bq    = (const float*)d_in[11];
    const float* g_Wr    = (const float*)d_in[12];
    const float* g_br    = (const float*)d_in[13];
    const float* g_V     = (const float*)d_in[14];
    const float* p_Wq    = (const float*)d_in[15];
    const float* p_bq    = (const float*)d_in[16];
    const float* p_Wr    = (const float*)d_in[17];
    const float* p_br    = (const float*)d_in[18];
    const float* p_V     = (const float*)d_in[19];
    const float* start   = (const float*)d_in[20];

    float* out       = (float*)d_out;
    float* out_probs = out;                              // [S,B,S]
    float* out_idx   = out + (size_t)S * B * S;          // [S,B] (as float)

    gumbelk <<<(S * B * S + 255) / 256, 256>>>();
    precompk<<<4, 256>>>(emb, enc_Wih, dec_Wih, start);

    encoderk<<<B / 4, 1024>>>(inputs, enc_Whh, enc_bih, enc_bhh,
                              g_Wr, g_br, p_Wr, p_br);

    decoderk<<<B / 4, 1024>>>(inputs, dec_Whh, dec_bih, dec_bhh,
                              g_Wq, g_bq, g_V, p_Wq, p_bq, p_V,
                              out_probs, out_idx);
}